// round 16
// baseline (speedup 1.0000x reference)
#include <cuda_runtime.h>
#include <math.h>

#define BB 4
#define CF 16
#define CLIPS 7
#define DC 256
#define KC 8192

typedef unsigned long long u64;
typedef unsigned int u32;

// ---------------- scratch ----------------
__device__ float g_y1[CLIPS*BB*32*CF*96*96];
__device__ float g_y2[CLIPS*BB*64*CF*48*48];
__device__ float g_y3[CLIPS*BB*128*CF*24*24];
__device__ float g_h [CLIPS*BB*32768];
__device__ float g_feat[BB*CLIPS*DC];
__device__ float g_quant[BB*CLIPS*DC];
__device__ int   g_tok[BB*CLIPS];
__device__ double g_stats[3*CLIPS*256];   // zero-init; finalize re-zeros (replay-safe)
__device__ float g_scale[CLIPS*128];
__device__ float g_shift[CLIPS*128];
__device__ float g_part_s[28*32];
__device__ int   g_part_i[28*32];
__device__ float g_gx[BB*6*768];
__device__ float g_ctx[BB*6*DC];

// packed bf16 hi/lo activations (u32 = hi16<<16 | lo16); padding never written -> 0
__device__ u32 g_xpk [CLIPS*BB*3*18*98*98];
__device__ u32 g_p1pk[28*32*18*50*50];
__device__ u32 g_p2pk[28*64*18*26*26];
// weights: pre-split hi-pair / lo-pair words (u32 = val(k+1)<<16 | val(k))
__device__ u32 g_w1hi[32*48],   g_w1lo[32*48];
__device__ u32 g_w2hi[64*432],  g_w2lo[64*432];
__device__ u32 g_w3hi[128*864], g_w3lo[128*864];

// ---------------- bf16 helpers ----------------
__device__ __forceinline__ u32 pkbf(float even_e, float odd_e) {
    u32 r; asm("cvt.rn.bf16x2.f32 %0, %1, %2;" : "=r"(r) : "f"(odd_e), "f"(even_e));
    return r;
}
__device__ __forceinline__ u32 packbf(float v) {
    u32 hb = pkbf(v, v) & 0xffffu;
    float hf = __uint_as_float(hb << 16);
    u32 lb = pkbf(v - hf, v - hf) & 0xffffu;
    return (hb << 16) | lb;
}
__device__ __forceinline__ void mma_bf(float (&d)[4],
                                       const u32 (&a)[4], u32 b0, u32 b1) {
    asm volatile(
        "mma.sync.aligned.m16n8k16.row.col.f32.bf16.bf16.f32 "
        "{%0,%1,%2,%3},{%4,%5,%6,%7},{%8,%9},{%0,%1,%2,%3};"
        : "+f"(d[0]), "+f"(d[1]), "+f"(d[2]), "+f"(d[3])
        : "r"(a[0]), "r"(a[1]), "r"(a[2]), "r"(a[3]), "r"(b0), "r"(b1));
}
__device__ __forceinline__ void ldsm4(u32 (&r)[4], u32 addr) {
    asm volatile("ldmatrix.sync.aligned.m8n8.x4.shared.b16 {%0,%1,%2,%3}, [%4];"
        : "=r"(r[0]), "=r"(r[1]), "=r"(r[2]), "=r"(r[3]) : "r"(addr));
}
__device__ __forceinline__ u32 smem_u32(const void* p) {
    u32 a; asm("{ .reg .u64 t; cvta.to.shared.u64 t, %1; cvt.u32.u64 %0, t; }" : "=r"(a) : "l"(p));
    return a;
}
__device__ __forceinline__ u32 prmt(u32 a, u32 b, u32 sel) {
    u32 r; asm("prmt.b32 %0,%1,%2,%3;" : "=r"(r) : "r"(a), "r"(b), "r"(sel));
    return r;
}

// smem word layout: B double-buffered [2][2][64][20] at 0; TUP at 5120
#define BW(b,s,r,w) ((b)*2560 + (s)*1280 + (r)*20 + (w))
#define TUPW 5120

// ============ conv3d k=3 pad=1 implicit GEMM, A direct-to-fragment, B smem ============
// grid: (M/256, COUT/NT, 28), block 256 (8 warps; warp w owns rows 32w..32w+31)
template<int CIN, int NT, int HS, int WS, int KREAL, int CHUNKS>
__global__ void __launch_bounds__(256,2)
convmma_k(const u32* __restrict__ xpk, long sampstr,
          const u32* __restrict__ whi, const u32* __restrict__ wlo,
          const float* __restrict__ bias,
          float* __restrict__ y, int coutall, int stage)
{
    constexpr int PL  = HS*WS;
    constexpr int PLC = CF*PL;
    constexpr int NT8 = NT/8;
    constexpr int NP  = NT8/2;
    constexpr int TPR = 256/NT;
    constexpr int KPT = 32/TPR;
    constexpr int JW  = KPT/2;
    constexpr int KPAD = CHUNKS*32;
    constexpr int KP2  = KPAD/2;
    constexpr int HP = HS+2, WP = WS+2;
    constexpr int HPWP = HP*WP;
    constexpr int CISTR = 18*HPWP;

    extern __shared__ u32 dsm[];

    const int t = threadIdx.x;
    const int warp = t >> 5, lane = t & 31;
    const int z = blockIdx.z, clip = z >> 2;
    const int co0 = blockIdx.y * NT;
    const u32 smb = smem_u32(dsm);

    // ---- tuple offsets (padded space), once ----
    for (int k = t; k < KPAD; k += 256) {
        int tp = 0;
        if (k < KREAL) {
            int ci = k/27; int r = k - ci*27;
            int kd = r/9;  int r2 = r - kd*9;
            int kh = r2/3; int kw = r2 - kh*3;
            tp = ci*CISTR + kd*HPWP + kh*WP + kw;
        }
        dsm[TUPW + k] = (u32)tp;
    }
    __syncthreads();

    // A fragment geometry
    const int q  = lane & 3;
    const int rl = lane >> 2;
    const u32* xbase = xpk + (long)z*sampstr;
    int roff[4];
    #pragma unroll
    for (int j = 0; j < 4; j++) {
        int pos = blockIdx.x*256 + warp*32 + rl + j*8;
        int dd = pos / PL; int rr2 = pos - dd*PL;
        int hh = rr2 / WS; int ww = rr2 - hh*WS;
        roff[j] = dd*HPWP + hh*WP + ww;
    }

    // B geometry
    const int bn  = t / TPR;
    const int bw0 = (t % TPR) * JW;
    const u32* wrowh = whi + (long)(co0 + bn)*KP2;
    const u32* wrowl = wlo + (long)(co0 + bn)*KP2;
    const int jq0 = (t + (t>>3)) & (JW - 1);

    // B ldsm lane geometry
    const int i7 = lane & 7, j3 = lane >> 3;
    const int b_row  = (j3 >> 1)*8 + i7;
    const int b_wsel = (j3 & 1) * 4;

    float acc[2][NT8][4];
    #pragma unroll
    for (int mi=0;mi<2;mi++)
        #pragma unroll
        for (int i=0;i<NT8;i++) { acc[mi][i][0]=0.f; acc[mi][i][1]=0.f; acc[mi][i][2]=0.f; acc[mi][i][3]=0.f; }

    u32 Ra0[16], Ra1[16];
    u32 Lbh[JW], Lbl[JW];

    auto ldg_half = [&](int c, int ks, u32 (&Ra)[16]) {
        int base = TUPW + c*32 + ks*16 + 2*q;
        int2 tA = *(const int2*)&dsm[base];
        int2 tB = *(const int2*)&dsm[base + 8];
        #pragma unroll
        for (int mi = 0; mi < 2; mi++) {
            #pragma unroll
            for (int rj = 0; rj < 2; rj++) {
                int ro = roff[mi*2 + rj];
                Ra[mi*8 + rj*4 + 0] = __ldg(xbase + ro + tA.x);
                Ra[mi*8 + rj*4 + 1] = __ldg(xbase + ro + tA.y);
                Ra[mi*8 + rj*4 + 2] = __ldg(xbase + ro + tB.x);
                Ra[mi*8 + rj*4 + 3] = __ldg(xbase + ro + tB.y);
            }
        }
    };
    auto ldg_B = [&](int c) {
        #pragma unroll
        for (int i = 0; i < JW; i++) {
            int jp = (jq0 + i) & (JW - 1);
            int wi = bw0 + jp;
            Lbh[i] = __ldg(wrowh + c*16 + wi);
            Lbl[i] = __ldg(wrowl + c*16 + wi);
        }
    };
    auto sts_B = [&](int buf) {
        #pragma unroll
        for (int i = 0; i < JW; i++) {
            int jp = (jq0 + i) & (JW - 1);
            int wi = bw0 + jp;
            dsm[BW(buf,0,bn,wi)] = Lbh[i];
            dsm[BW(buf,1,bn,wi)] = Lbl[i];
        }
    };
    // mma on one half-chunk; term-major ordering within p breaks acc chains
    // (each accumulator still receives hh -> hl -> lh in order: bit-identical)
    auto mma_half = [&](const u32 (&Ra)[16], int buf, int ks) {
        u32 ah[2][4], al[2][4];
        #pragma unroll
        for (int mi = 0; mi < 2; mi++) {
            ah[mi][0] = prmt(Ra[mi*8+0], Ra[mi*8+1], 0x7632u);
            al[mi][0] = prmt(Ra[mi*8+0], Ra[mi*8+1], 0x5410u);
            ah[mi][1] = prmt(Ra[mi*8+4], Ra[mi*8+5], 0x7632u);
            al[mi][1] = prmt(Ra[mi*8+4], Ra[mi*8+5], 0x5410u);
            ah[mi][2] = prmt(Ra[mi*8+2], Ra[mi*8+3], 0x7632u);
            al[mi][2] = prmt(Ra[mi*8+2], Ra[mi*8+3], 0x5410u);
            ah[mi][3] = prmt(Ra[mi*8+6], Ra[mi*8+7], 0x7632u);
            al[mi][3] = prmt(Ra[mi*8+6], Ra[mi*8+7], 0x5410u);
        }
        #pragma unroll
        for (int p = 0; p < NP; p++) {
            u32 bh[4], bl[4];
            ldsm4(bh, smb + 4u*BW(buf, 0, p*16 + b_row, ks*8 + b_wsel));
            ldsm4(bl, smb + 4u*BW(buf, 1, p*16 + b_row, ks*8 + b_wsel));
            // term hh
            #pragma unroll
            for (int mi = 0; mi < 2; mi++) {
                mma_bf(acc[mi][2*p],   ah[mi], bh[0], bh[1]);
                mma_bf(acc[mi][2*p+1], ah[mi], bh[2], bh[3]);
            }
            // term hl
            #pragma unroll
            for (int mi = 0; mi < 2; mi++) {
                mma_bf(acc[mi][2*p],   ah[mi], bl[0], bl[1]);
                mma_bf(acc[mi][2*p+1], ah[mi], bl[2], bl[3]);
            }
            // term lh
            #pragma unroll
            for (int mi = 0; mi < 2; mi++) {
                mma_bf(acc[mi][2*p],   al[mi], bh[0], bh[1]);
                mma_bf(acc[mi][2*p+1], al[mi], bh[2], bh[3]);
            }
        }
    };

    // prologue
    ldg_B(0);
    sts_B(0);
    ldg_half(0, 0, Ra0);
    __syncthreads();

    #pragma unroll 1
    for (int c = 0; c < CHUNKS; c++) {
        const int buf = c & 1;
        const bool more = (c + 1 < CHUNKS);
        ldg_half(c, 1, Ra1);
        if (more) ldg_B(c + 1);
        mma_half(Ra0, buf, 0);
        if (more) ldg_half(c + 1, 0, Ra0);
        mma_half(Ra1, buf, 1);
        if (more) sts_B(buf ^ 1);
        __syncthreads();
    }

    // ---- epilogue: bias, store, fused BN stats ----
    float4* s_red = (float4*)dsm;
    const int r_base = blockIdx.x*256 + warp*32 + rl;
    float* yb = y + ((long)z*coutall + co0)*(long)PLC;
    #pragma unroll
    for (int nt = 0; nt < NT8; nt++) {
        int c0 = nt*8 + 2*q;
        float b0 = __ldg(&bias[co0 + c0]);
        float b1 = __ldg(&bias[co0 + c0 + 1]);
        float se = 0.f, so = 0.f, qe = 0.f, qo = 0.f;
        #pragma unroll
        for (int mi = 0; mi < 2; mi++) {
            float v00 = acc[mi][nt][0] + b0;
            float v01 = acc[mi][nt][1] + b1;
            float v10 = acc[mi][nt][2] + b0;
            float v11 = acc[mi][nt][3] + b1;
            int r0 = r_base + mi*16;
            yb[(long)c0*PLC + r0]         = v00;
            yb[(long)(c0+1)*PLC + r0]     = v01;
            yb[(long)c0*PLC + r0 + 8]     = v10;
            yb[(long)(c0+1)*PLC + r0 + 8] = v11;
            se += v00 + v10;  so += v01 + v11;
            qe += v00*v00 + v10*v10;  qo += v01*v01 + v11*v11;
        }
        #pragma unroll
        for (int o = 4; o <= 16; o <<= 1) {
            se += __shfl_xor_sync(0xffffffff, se, o);
            so += __shfl_xor_sync(0xffffffff, so, o);
            qe += __shfl_xor_sync(0xffffffff, qe, o);
            qo += __shfl_xor_sync(0xffffffff, qo, o);
        }
        if (lane < 4) s_red[warp*32 + nt*4 + lane] = make_float4(se, so, qe, qo);
    }
    __syncthreads();
    if (t < NT) {
        int nt = t >> 3, cp = (t & 7) >> 1, odd = t & 1;
        double ds = 0.0, dq = 0.0;
        #pragma unroll
        for (int w8 = 0; w8 < 8; w8++) {
            float4 f = s_red[w8*32 + nt*4 + cp];
            ds += (double)(odd ? f.y : f.x);
            dq += (double)(odd ? f.w : f.z);
        }
        double* st = g_stats + (long)stage*CLIPS*256 + clip*256;
        atomicAdd(&st[co0 + t], ds);
        atomicAdd(&st[128 + co0 + t], dq);
    }
}

// ---------------- pack kernels ----------------
__global__ void pack_x_k(const float* __restrict__ x, int base, int count)
{
    int idx = blockIdx.x*blockDim.x + threadIdx.x;
    if (idx >= count) return;
    idx += base;
    int w = idx % 96; int t2 = idx / 96;
    int h = t2 % 96; t2 /= 96;
    int d = t2 % 16; t2 /= 16;
    int ci = t2 % 3; t2 /= 3;
    int nb = t2 % 4; int clip = t2 / 4;
    float v = x[(((long)(nb*3+ci)*64 + clip*8 + d)*96 + h)*96 + w];
    g_xpk[((((long)(clip*4+nb)*3 + ci)*18 + d+1)*98 + h+1)*98 + w+1] = packbf(v);
}

__global__ void pack_w_all_k(const float* __restrict__ w1, const float* __restrict__ w2,
                             const float* __restrict__ w3)
{
    int idx = blockIdx.x*blockDim.x + threadIdx.x;
    const float* w; u32 *dh, *dl; int kreal, kp2, rel;
    if (idx < 1536)        { w = w1; dh = g_w1hi; dl = g_w1lo; kreal = 81;   kp2 = 48;  rel = idx; }
    else if (idx < 29184)  { w = w2; dh = g_w2hi; dl = g_w2lo; kreal = 864;  kp2 = 432; rel = idx - 1536; }
    else if (idx < 139776) { w = w3; dh = g_w3hi; dl = g_w3lo; kreal = 1728; kp2 = 864; rel = idx - 29184; }
    else return;
    int co = rel / kp2, kp = rel - co*kp2;
    int k0 = 2*kp;
    float v0 = (k0   < kreal) ? w[(long)co*kreal + k0]   : 0.f;
    float v1 = (k0+1 < kreal) ? w[(long)co*kreal + k0+1] : 0.f;
    u32 p0 = packbf(v0), p1 = packbf(v1);
    dh[rel] = ((p1 >> 16) << 16) | (p0 >> 16);
    dl[rel] = ((p1 & 0xffffu) << 16) | (p0 & 0xffffu);
}

// ---------------- finalize stats (re-zeros accumulators) ----------------
__global__ void finalize_stats_k(const float* __restrict__ gma, const float* __restrict__ bet,
                                 int stage, int C, double cnt)
{
    int clip = blockIdx.x, c = threadIdx.x;
    if (c < C) {
        double* st = g_stats + (long)stage*CLIPS*256 + clip*256;
        double m = st[c] / cnt;
        double v = st[128 + c] / cnt - m*m;
        st[c] = 0.0; st[128 + c] = 0.0;
        double sc = (double)gma[c] / sqrt(v + 1e-5);
        g_scale[clip*128 + c] = (float)sc;
        g_shift[clip*128 + c] = (float)((double)bet[c] - m*sc);
    }
}

// ---------------- BN + ReLU + maxpool(1,2,2) -> packed padded out (templated) ----------------
template<int C, int H, int W>
__global__ void bn_maxpool_pk_k(const float* __restrict__ y, u32* __restrict__ out)
{
    constexpr int HO = H/2, WO = W/2;
    constexpr int POH = HO+2, POW = WO+2;
    int o = blockIdx.x*256 + threadIdx.x;
    int wo = o % WO; int t = o / WO;
    int ho = t % HO; t /= HO;
    int d  = t % CF; t /= CF;
    int c  = t % C;  t /= C;
    int clip = t >> 2;
    float sc = g_scale[clip*128 + c], sh = g_shift[clip*128 + c];
    const float* p = y + (((long)(t*C + c)*CF + d)*H + 2*ho)*W + 2*wo;
    float2 r0 = *(const float2*)p;
    float2 r1 = *(const float2*)(p + W);
    float a0 = fmaxf(fmaf(sc, r0.x, sh), 0.f);
    float a1 = fmaxf(fmaf(sc, r0.y, sh), 0.f);
    float a2 = fmaxf(fmaf(sc, r1.x, sh), 0.f);
    float a3 = fmaxf(fmaf(sc, r1.y, sh), 0.f);
    float v = fmaxf(fmaxf(a0,a1), fmaxf(a2,a3));
    out[(((long)(t*C + c)*18 + d+1)*POH + ho+1)*POW + wo+1] = packbf(v);
}

// ---------------- BN + ReLU + avgpool 6x6 -> flattened h ----------------
__global__ void bn_avgpool_k(const float* __restrict__ y)
{
    int idx = blockIdx.x*blockDim.x + threadIdx.x;
    if (idx >= CLIPS*BB*128*16*16) return;
    int wo = idx & 3;
    int ho = (idx >> 2) & 3;
    int d  = (idx >> 4) & 15;
    int c  = (idx >> 8) & 127;
    int n  = (idx >> 15) & 3;
    int clip = idx >> 17;
    float sc = g_scale[clip*128 + c], sh = g_shift[clip*128 + c];
    const float* p = y + ((((long)(clip*BB+n)*128 + c)*CF + d)*24 + 6*ho)*24 + 6*wo;
    float s = 0.f;
    #pragma unroll
    for (int i=0;i<6;i++)
        #pragma unroll
        for (int j=0;j<6;j++)
            s += fmaxf(fmaf(sc, p[i*24+j], sh), 0.f);
    g_h[(long)(clip*BB+n)*32768 + c*256 + d*16 + ho*4 + wo] = s * (1.f/36.f);
}

// ---------------- batched projection ----------------
__global__ void proj_k(const float* __restrict__ pw, const float* __restrict__ pb)
{
    int co = blockIdx.x;
    int t = threadIdx.x;
    float part[28];
    #pragma unroll
    for (int r=0;r<28;r++) part[r] = 0.f;
    const float* wrow = pw + (long)co*32768;
    for (int j = t; j < 32768; j += 256) {
        float wv = wrow[j];
        #pragma unroll
        for (int r=0;r<28;r++)
            part[r] = fmaf(wv, g_h[(long)r*32768 + j], part[r]);
    }
    #pragma unroll
    for (int r=0;r<28;r++)
        #pragma unroll
        for (int o=16;o>0;o>>=1)
            part[r] += __shfl_xor_sync(0xffffffff, part[r], o);
    __shared__ float sred[28][8];
    int wa = t >> 5, l = t & 31;
    if (l == 0) {
        #pragma unroll
        for (int r=0;r<28;r++) sred[r][wa] = part[r];
    }
    __syncthreads();
    if (t < 28) {
        float a = 0.f;
        #pragma unroll
        for (int k=0;k<8;k++) a += sred[t][k];
        int clip = t >> 2, b_ = t & 3;
        g_feat[(b_*CLIPS + clip)*DC + co] = a + pb[co];
    }
}

// ---------------- VQ argmin ----------------
__global__ void quant_score_k(const float* __restrict__ cb)
{
    int row = blockIdx.x;
    int k = blockIdx.y*256 + threadIdx.x;
    __shared__ float sf[DC];
    sf[threadIdx.x] = g_feat[row*DC + threadIdx.x];
    __syncthreads();
    const float4* c4 = (const float4*)(cb + (long)k*DC);
    const float4* f4 = (const float4*)sf;
    float dot = 0.f, cn = 0.f;
    #pragma unroll 8
    for (int j=0; j<64; j++) {
        float4 c = c4[j]; float4 f = f4[j];
        dot = fmaf(c.x,f.x,dot); dot = fmaf(c.y,f.y,dot);
        dot = fmaf(c.z,f.z,dot); dot = fmaf(c.w,f.w,dot);
        cn  = fmaf(c.x,c.x,cn);  cn  = fmaf(c.y,c.y,cn);
        cn  = fmaf(c.z,c.z,cn);  cn  = fmaf(c.w,c.w,cn);
    }
    float score = cn - 2.f*dot;
    __shared__ float ss[256];
    __shared__ int   si[256];
    ss[threadIdx.x] = score; si[threadIdx.x] = k;
    __syncthreads();
    for (int o=128; o>0; o>>=1) {
        if (threadIdx.x < o) {
            float s2 = ss[threadIdx.x+o]; int i2 = si[threadIdx.x+o];
            if (s2 < ss[threadIdx.x] || (s2 == ss[threadIdx.x] && i2 < si[threadIdx.x])) {
                ss[threadIdx.x] = s2; si[threadIdx.x] = i2;
            }
        }
        __syncthreads();
    }
    if (threadIdx.x == 0) { g_part_s[row*32+blockIdx.y] = ss[0]; g_part_i[row*32+blockIdx.y] = si[0]; }
}

__global__ void quant_reduce_k(const float* __restrict__ cb)
{
    int row = blockIdx.x;
    __shared__ int bi;
    if (threadIdx.x == 0) {
        float s = g_part_s[row*32]; int i = g_part_i[row*32];
        for (int j=1; j<32; j++) {
            float s2 = g_part_s[row*32+j]; int i2 = g_part_i[row*32+j];
            if (s2 < s || (s2 == s && i2 < i)) { s = s2; i = i2; }
        }
        g_tok[row] = i; bi = i;
    }
    __syncthreads();
    const float* crow = cb + (long)bi*DC;
    for (int j = threadIdx.x; j < DC; j += blockDim.x)
        g_quant[row*DC+j] = crow[j];
}

// ---------------- GRU input gates ----------------
__global__ void gru_gx_k(const float* __restrict__ wih, const float* __restrict__ bih)
{
    int bt = blockIdx.x;
    int g = blockIdx.y*128 + threadIdx.x;
    int b_ = bt/6, t = bt%6;
    __shared__ float sq[DC];
    sq[threadIdx.x]     = g_quant[(b_*CLIPS+t)*DC + threadIdx.x];
    sq[threadIdx.x+128] = g_quant[(b_*CLIPS+t)*DC + 128 + threadIdx.x];
    __syncthreads();
    const float4* w4 = (const float4*)(wih + (long)g*DC);
    const float4* q4 = (const float4*)sq;
    float a = bih[g];
    #pragma unroll 8
    for (int j=0;j<64;j++) {
        float4 w = w4[j], q = q4[j];
        a = fmaf(w.x,q.x,a); a = fmaf(w.y,q.y,a); a = fmaf(w.z,q.z,a); a = fmaf(w.w,q.w,a);
    }
    g_gx[bt*768 + g] = a;
}

// ---------------- fused GRU recurrence ----------------
__global__ void gru_fused_k(const float* __restrict__ whh, const float* __restrict__ bhh)
{
    int b_ = blockIdx.x, d = threadIdx.x;
    __shared__ float s_h[DC];
    s_h[d] = 0.f;
    __syncthreads();
    const float4* wr4 = (const float4*)(whh + (long)d*DC);
    const float4* wz4 = (const float4*)(whh + (long)(256+d)*DC);
    const float4* wn4 = (const float4*)(whh + (long)(512+d)*DC);
    float br = bhh[d], bz = bhh[256+d], bn_ = bhh[512+d];
    for (int t=0; t<6; t++) {
        float hr = br, hz = bz, hn = bn_;
        const float4* h4 = (const float4*)s_h;
        #pragma unroll 8
        for (int j=0; j<64; j++) {
            float4 h = h4[j];
            float4 a = wr4[j], bzv = wz4[j], c = wn4[j];
            hr = fmaf(a.x,h.x,hr); hr = fmaf(a.y,h.y,hr); hr = fmaf(a.z,h.z,hr); hr = fmaf(a.w,h.w,hr);
            hz = fmaf(bzv.x,h.x,hz); hz = fmaf(bzv.y,h.y,hz); hz = fmaf(bzv.z,h.z,hz); hz = fmaf(bzv.w,h.w,hz);
            hn = fmaf(c.x,h.x,hn); hn = fmaf(c.y,h.y,hn); hn = fmaf(c.z,h.z,hn); hn = fmaf(c.w,h.w,hn);
        }
        int bt = b_*6 + t;
        float xr = g_gx[bt*768 + d];
        float xz = g_gx[bt*768 + 256 + d];
        float xn = g_gx[bt*768 + 512 + d];
        float r = 1.f/(1.f + expf(-(xr+hr)));
        float z = 1.f/(1.f + expf(-(xz+hz)));
        float nn = tanhf(xn + r*hn);
        float h2 = (1.f - z)*nn + z*s_h[d];
        __syncthreads();
        s_h[d] = h2;
        g_ctx[bt*DC + d] = h2;
        __syncthreads();
    }
}

// ---------------- fused losses + output assembly ----------------
__global__ void loss_final_k(float* __restrict__ out)
{
    int t = threadIdx.x;
    float s0 = 0.f, s1 = 0.f;
    for (int i = t; i < BB*CLIPS*DC; i += 256) {
        float dd = g_feat[i] - g_quant[i];
        s0 = fmaf(dd, dd, s0);
    }
    for (int i = t; i < BB*6*DC; i += 256) {
        int d = i % DC; int tt = (i/DC) % 6; int b_ = i/(6*DC);
        float diff = g_ctx[i] - g_feat[(b_*CLIPS + tt + 1)*DC + d];
        s1 = fmaf(diff, diff, s1);
    }
    __shared__ float sh0[256], sh1[256];
    sh0[t] = s0; sh1[t] = s1; __syncthreads();
    for (int o=128; o>0; o>>=1) {
        if (t < o) { sh0[t] += sh0[t+o]; sh1[t] += sh1[t+o]; }
        __syncthreads();
    }
    for (int i = t; i < BB*CLIPS; i += 256) out[i] = (float)g_tok[i];
    for (int i = t; i < BB*CLIPS*DC; i += 256) out[28 + i] = g_quant[i];
    if (t == 0) {
        float c = sh0[0] / (float)(BB*CLIPS*DC);
        float x = sh1[0] / (float)(BB*6*DC);
        out[28 + 7168 + 0] = c;
        out[28 + 7168 + 1] = c;
        out[28 + 7168 + 2] = x;
        out[28 + 7168 + 3] = c + 0.25f*c + 0.1f*x;
    }
}

// ---------------- host launcher ----------------
extern "C" void kernel_launch(void* const* d_in, const int* in_sizes, int n_in,
                              void* d_out, int out_size)
{
    const float* x   = (const float*)d_in[0];
    const float* c1w = (const float*)d_in[1];
    const float* c1b = (const float*)d_in[2];
    const float* g1  = (const float*)d_in[3];
    const float* b1  = (const float*)d_in[4];
    const float* c2w = (const float*)d_in[5];
    const float* c2b = (const float*)d_in[6];
    const float* g2  = (const float*)d_in[7];
    const float* b2  = (const float*)d_in[8];
    const float* c3w = (const float*)d_in[9];
    const float* c3b = (const float*)d_in[10];
    const float* g3  = (const float*)d_in[11];
    const float* b3  = (const float*)d_in[12];
    const float* pw  = (const float*)d_in[13];
    const float* pb  = (const float*)d_in[14];
    const float* cb  = (const float*)d_in[15];
    const float* wih = (const float*)d_in[16];
    const float* whh = (const float*)d_in[17];
    const float* bih = (const float*)d_in[18];
    const float* bhh = (const float*)d_in[19];
    float* out = (float*)d_out;

    float *y1, *y2, *y3;
    u32 *xpk, *p1pk, *p2pk;
    u32 *w1hi, *w1lo, *w2hi, *w2lo, *w3hi, *w3lo;
    cudaGetSymbolAddress((void**)&y1, g_y1);
    cudaGetSymbolAddress((void**)&y2, g_y2);
    cudaGetSymbolAddress((void**)&y3, g_y3);
    cudaGetSymbolAddress((void**)&xpk, g_xpk);
    cudaGetSymbolAddress((void**)&p1pk, g_p1pk);
    cudaGetSymbolAddress((void**)&p2pk, g_p2pk);
    cudaGetSymbolAddress((void**)&w1hi, g_w1hi);
    cudaGetSymbolAddress((void**)&w1lo, g_w1lo);
    cudaGetSymbolAddress((void**)&w2hi, g_w2hi);
    cudaGetSymbolAddress((void**)&w2lo, g_w2lo);
    cudaGetSymbolAddress((void**)&w3hi, g_w3hi);
    cudaGetSymbolAddress((void**)&w3lo, g_w3lo);

    const int sm1 = (TUPW + 96)   * 4;
    const int sm2 = (TUPW + 864)  * 4;
    const int sm3 = (TUPW + 1728) * 4;
    cudaFuncSetAttribute(convmma_k<3,32,96,96,81,3>,
                         cudaFuncAttributeMaxDynamicSharedMemorySize, sm1);
    cudaFuncSetAttribute(convmma_k<32,64,48,48,864,27>,
                         cudaFuncAttributeMaxDynamicSharedMemorySize, sm2);
    cudaFuncSetAttribute(convmma_k<64,64,24,24,1728,54>,
                         cudaFuncAttributeMaxDynamicSharedMemorySize, sm3);

    // ---- pack (conv1 stays at launch idx 3 for ncu) ----
    const int XTOT = CLIPS*BB*3*16*96*96;
    const int XHALF = XTOT/2;
    pack_x_k<<<(XHALF + 255)/256, 256>>>(x, 0, XHALF);                 // 0
    pack_x_k<<<(XTOT - XHALF + 255)/256, 256>>>(x, XHALF, XTOT-XHALF); // 1
    pack_w_all_k<<<(139776 + 255)/256, 256>>>(c1w, c2w, c3w);          // 2

    // stage 1: conv1 -> [28][32][16][96][96]                          // 3 (profiled)
    convmma_k<3,32,96,96,81,3><<<dim3(576,1,28), 256, sm1>>>(
        xpk, (long)3*18*98*98, w1hi, w1lo, c1b, y1, 32, 0);
    finalize_stats_k<<<CLIPS,128>>>(g1, b1, 0, 32, (double)(BB*16*96*96));
    bn_maxpool_pk_k<32,96,96><<<129024,256>>>(y1, p1pk);

    // stage 2: conv2 -> [28][64][16][48][48]
    convmma_k<32,64,48,48,864,27><<<dim3(144,1,28), 256, sm2>>>(
        p1pk, (long)32*18*50*50, w2hi, w2lo, c2b, y2, 64, 1);
    finalize_stats_k<<<CLIPS,128>>>(g2, b2, 1, 64, (double)(BB*16*48*48));
    bn_maxpool_pk_k<64,48,48><<<64512,256>>>(y2, p2pk);

    // stage 3: conv3 -> [28][128][16][24][24]
    convmma_k<64,64,24,24,1728,54><<<dim3(36,2,28), 256, sm3>>>(
        p2pk, (long)64*18*26*26, w3hi, w3lo, c3b, y3, 128, 2);
    finalize_stats_k<<<CLIPS,128>>>(g3, b3, 2, 128, (double)(BB*16*24*24));
    bn_avgpool_k<<<3584,256>>>(y3);

    // projection + VQ + GRU + losses
    proj_k<<<256,256>>>(pw, pb);
    quant_score_k<<<dim3(28,32),256>>>(cb);
    quant_reduce_k<<<28,64>>>(cb);
    gru_gx_k<<<dim3(24,6),128>>>(wih, bih);
    gru_fused_k<<<4,256>>>(whh, bhh);
    loss_final_k<<<1,256>>>(out);
}

// round 17
// speedup vs baseline: 1.0404x; 1.0404x over previous
#include <cuda_runtime.h>
#include <math.h>

#define BB 4
#define CF 16
#define CLIPS 7
#define DC 256
#define KC 8192

typedef unsigned long long u64;
typedef unsigned int u32;

// ---------------- scratch ----------------
__device__ float g_y1[CLIPS*BB*32*CF*96*96];
__device__ float g_y2[CLIPS*BB*64*CF*48*48];
__device__ float g_y3[CLIPS*BB*128*CF*24*24];
__device__ float g_h [CLIPS*BB*32768];
__device__ float g_feat[BB*CLIPS*DC];
__device__ float g_quant[BB*CLIPS*DC];
__device__ int   g_tok[BB*CLIPS];
__device__ double g_stats[3*CLIPS*256];   // zero-init; finalize re-zeros (replay-safe)
__device__ float g_scale[CLIPS*128];
__device__ float g_shift[CLIPS*128];
__device__ float g_part_s[28*32];
__device__ int   g_part_i[28*32];
__device__ float g_gx[BB*6*768];
__device__ float g_ctx[BB*6*DC];

// packed bf16 hi/lo activations (u32 = hi16<<16 | lo16); padding never written -> 0
__device__ u32 g_xpk [CLIPS*BB*3*18*98*98];
__device__ u32 g_p1pk[28*32*18*50*50];
__device__ u32 g_p2pk[28*64*18*26*26];
// weights: pre-split hi-pair / lo-pair words (u32 = val(k+1)<<16 | val(k))
__device__ u32 g_w1hi[32*48],   g_w1lo[32*48];
__device__ u32 g_w2hi[64*432],  g_w2lo[64*432];
__device__ u32 g_w3hi[128*864], g_w3lo[128*864];

// ---------------- bf16 helpers ----------------
__device__ __forceinline__ u32 pkbf(float even_e, float odd_e) {
    u32 r; asm("cvt.rn.bf16x2.f32 %0, %1, %2;" : "=r"(r) : "f"(odd_e), "f"(even_e));
    return r;
}
__device__ __forceinline__ u32 packbf(float v) {
    u32 hb = pkbf(v, v) & 0xffffu;
    float hf = __uint_as_float(hb << 16);
    u32 lb = pkbf(v - hf, v - hf) & 0xffffu;
    return (hb << 16) | lb;
}
__device__ __forceinline__ void mma_bf(float (&d)[4],
                                       const u32 (&a)[4], u32 b0, u32 b1) {
    asm volatile(
        "mma.sync.aligned.m16n8k16.row.col.f32.bf16.bf16.f32 "
        "{%0,%1,%2,%3},{%4,%5,%6,%7},{%8,%9},{%0,%1,%2,%3};"
        : "+f"(d[0]), "+f"(d[1]), "+f"(d[2]), "+f"(d[3])
        : "r"(a[0]), "r"(a[1]), "r"(a[2]), "r"(a[3]), "r"(b0), "r"(b1));
}
__device__ __forceinline__ void ldsm4(u32 (&r)[4], u32 addr) {
    asm volatile("ldmatrix.sync.aligned.m8n8.x4.shared.b16 {%0,%1,%2,%3}, [%4];"
        : "=r"(r[0]), "=r"(r[1]), "=r"(r[2]), "=r"(r[3]) : "r"(addr));
}
__device__ __forceinline__ u32 smem_u32(const void* p) {
    u32 a; asm("{ .reg .u64 t; cvta.to.shared.u64 t, %1; cvt.u32.u64 %0, t; }" : "=r"(a) : "l"(p));
    return a;
}
__device__ __forceinline__ u32 prmt(u32 a, u32 b, u32 sel) {
    u32 r; asm("prmt.b32 %0,%1,%2,%3;" : "=r"(r) : "r"(a), "r"(b), "r"(sel));
    return r;
}
__device__ __forceinline__ void cpasync4(u32 saddr, const u32* g) {
    asm volatile("cp.async.ca.shared.global [%0], [%1], 4;" :: "r"(saddr), "l"(g) : "memory");
}
__device__ __forceinline__ void cpcommit() {
    asm volatile("cp.async.commit_group;" ::: "memory");
}
__device__ __forceinline__ void cpwait0() {
    asm volatile("cp.async.wait_group 0;" ::: "memory");
}

// smem word layout: B double-buffered [2][2][64][20] at 0; TUP at 5120
#define BW(b,s,r,w) ((b)*2560 + (s)*1280 + (r)*20 + (w))
#define TUPW 5120

// ============ conv3d k=3 pad=1 implicit GEMM, A direct-to-fragment, B cp.async ============
// grid: (M/256, COUT/NT, 28), block 256 (8 warps; warp w owns rows 32w..32w+31)
template<int CIN, int NT, int HS, int WS, int KREAL, int CHUNKS, int MAXB>
__global__ void __launch_bounds__(256, MAXB)
convmma_k(const u32* __restrict__ xpk, long sampstr,
          const u32* __restrict__ whi, const u32* __restrict__ wlo,
          const float* __restrict__ bias,
          float* __restrict__ y, int coutall, int stage)
{
    constexpr int PL  = HS*WS;
    constexpr int PLC = CF*PL;
    constexpr int NT8 = NT/8;
    constexpr int NP  = NT8/2;
    constexpr int TPR = 256/NT;
    constexpr int KPT = 32/TPR;
    constexpr int JW  = KPT/2;
    constexpr int KPAD = CHUNKS*32;
    constexpr int KP2  = KPAD/2;
    constexpr int HP = HS+2, WP = WS+2;
    constexpr int HPWP = HP*WP;
    constexpr int CISTR = 18*HPWP;

    extern __shared__ u32 dsm[];

    const int t = threadIdx.x;
    const int warp = t >> 5, lane = t & 31;
    const int z = blockIdx.z, clip = z >> 2;
    const int co0 = blockIdx.y * NT;
    const u32 smb = smem_u32(dsm);

    // ---- tuple offsets (padded space), once ----
    for (int k = t; k < KPAD; k += 256) {
        int tp = 0;
        if (k < KREAL) {
            int ci = k/27; int r = k - ci*27;
            int kd = r/9;  int r2 = r - kd*9;
            int kh = r2/3; int kw = r2 - kh*3;
            tp = ci*CISTR + kd*HPWP + kh*WP + kw;
        }
        dsm[TUPW + k] = (u32)tp;
    }
    __syncthreads();

    // A fragment geometry
    const int q  = lane & 3;
    const int rl = lane >> 2;
    const u32* xbase = xpk + (long)z*sampstr;
    int roff[4];
    #pragma unroll
    for (int j = 0; j < 4; j++) {
        int pos = blockIdx.x*256 + warp*32 + rl + j*8;
        int dd = pos / PL; int rr2 = pos - dd*PL;
        int hh = rr2 / WS; int ww = rr2 - hh*WS;
        roff[j] = dd*HPWP + hh*WP + ww;
    }

    // B geometry (cp.async direct to smem)
    const int bn  = t / TPR;
    const int bw0 = (t % TPR) * JW;
    const u32* wrowh = whi + (long)(co0 + bn)*KP2;
    const u32* wrowl = wlo + (long)(co0 + bn)*KP2;
    const int jq0 = (t + (t>>3)) & (JW - 1);

    // B ldsm lane geometry
    const int i7 = lane & 7, j3 = lane >> 3;
    const int b_row  = (j3 >> 1)*8 + i7;
    const int b_wsel = (j3 & 1) * 4;

    float acc[2][NT8][4];
    #pragma unroll
    for (int mi=0;mi<2;mi++)
        #pragma unroll
        for (int i=0;i<NT8;i++) { acc[mi][i][0]=0.f; acc[mi][i][1]=0.f; acc[mi][i][2]=0.f; acc[mi][i][3]=0.f; }

    u32 Ra0[16], Ra1[16];

    auto ldg_half = [&](int c, int ks, u32 (&Ra)[16]) {
        int base = TUPW + c*32 + ks*16 + 2*q;
        int2 tA = *(const int2*)&dsm[base];
        int2 tB = *(const int2*)&dsm[base + 8];
        #pragma unroll
        for (int mi = 0; mi < 2; mi++) {
            #pragma unroll
            for (int rj = 0; rj < 2; rj++) {
                int ro = roff[mi*2 + rj];
                Ra[mi*8 + rj*4 + 0] = __ldg(xbase + ro + tA.x);
                Ra[mi*8 + rj*4 + 1] = __ldg(xbase + ro + tA.y);
                Ra[mi*8 + rj*4 + 2] = __ldg(xbase + ro + tB.x);
                Ra[mi*8 + rj*4 + 3] = __ldg(xbase + ro + tB.y);
            }
        }
    };
    auto cpasync_B = [&](int c, int buf) {
        #pragma unroll
        for (int i = 0; i < JW; i++) {
            int jp = (jq0 + i) & (JW - 1);
            int wi = bw0 + jp;
            cpasync4(smb + 4u*BW(buf,0,bn,wi), wrowh + c*16 + wi);
            cpasync4(smb + 4u*BW(buf,1,bn,wi), wrowl + c*16 + wi);
        }
        cpcommit();
    };
    // mma on one half-chunk (R15 ordering)
    auto mma_half = [&](const u32 (&Ra)[16], int buf, int ks) {
        u32 ah[2][4], al[2][4];
        #pragma unroll
        for (int mi = 0; mi < 2; mi++) {
            ah[mi][0] = prmt(Ra[mi*8+0], Ra[mi*8+1], 0x7632u);
            al[mi][0] = prmt(Ra[mi*8+0], Ra[mi*8+1], 0x5410u);
            ah[mi][1] = prmt(Ra[mi*8+4], Ra[mi*8+5], 0x7632u);
            al[mi][1] = prmt(Ra[mi*8+4], Ra[mi*8+5], 0x5410u);
            ah[mi][2] = prmt(Ra[mi*8+2], Ra[mi*8+3], 0x7632u);
            al[mi][2] = prmt(Ra[mi*8+2], Ra[mi*8+3], 0x5410u);
            ah[mi][3] = prmt(Ra[mi*8+6], Ra[mi*8+7], 0x7632u);
            al[mi][3] = prmt(Ra[mi*8+6], Ra[mi*8+7], 0x5410u);
        }
        #pragma unroll
        for (int p = 0; p < NP; p++) {
            u32 bh[4], bl[4];
            ldsm4(bh, smb + 4u*BW(buf, 0, p*16 + b_row, ks*8 + b_wsel));
            ldsm4(bl, smb + 4u*BW(buf, 1, p*16 + b_row, ks*8 + b_wsel));
            #pragma unroll
            for (int mi = 0; mi < 2; mi++) {
                mma_bf(acc[mi][2*p],   ah[mi], bh[0], bh[1]);
                mma_bf(acc[mi][2*p],   ah[mi], bl[0], bl[1]);
                mma_bf(acc[mi][2*p],   al[mi], bh[0], bh[1]);
                mma_bf(acc[mi][2*p+1], ah[mi], bh[2], bh[3]);
                mma_bf(acc[mi][2*p+1], ah[mi], bl[2], bl[3]);
                mma_bf(acc[mi][2*p+1], al[mi], bh[2], bh[3]);
            }
        }
    };

    // prologue
    cpasync_B(0, 0);
    ldg_half(0, 0, Ra0);
    cpwait0();
    __syncthreads();

    #pragma unroll 1
    for (int c = 0; c < CHUNKS; c++) {
        const int buf = c & 1;
        const bool more = (c + 1 < CHUNKS);
        ldg_half(c, 1, Ra1);
        if (more) cpasync_B(c + 1, buf ^ 1);
        mma_half(Ra0, buf, 0);
        if (more) ldg_half(c + 1, 0, Ra0);
        mma_half(Ra1, buf, 1);
        if (more) cpwait0();
        __syncthreads();
    }

    // ---- epilogue: bias, store, fused BN stats ----
    float4* s_red = (float4*)dsm;
    const int r_base = blockIdx.x*256 + warp*32 + rl;
    float* yb = y + ((long)z*coutall + co0)*(long)PLC;
    #pragma unroll
    for (int nt = 0; nt < NT8; nt++) {
        int c0 = nt*8 + 2*q;
        float b0 = __ldg(&bias[co0 + c0]);
        float b1 = __ldg(&bias[co0 + c0 + 1]);
        float se = 0.f, so = 0.f, qe = 0.f, qo = 0.f;
        #pragma unroll
        for (int mi = 0; mi < 2; mi++) {
            float v00 = acc[mi][nt][0] + b0;
            float v01 = acc[mi][nt][1] + b1;
            float v10 = acc[mi][nt][2] + b0;
            float v11 = acc[mi][nt][3] + b1;
            int r0 = r_base + mi*16;
            yb[(long)c0*PLC + r0]         = v00;
            yb[(long)(c0+1)*PLC + r0]     = v01;
            yb[(long)c0*PLC + r0 + 8]     = v10;
            yb[(long)(c0+1)*PLC + r0 + 8] = v11;
            se += v00 + v10;  so += v01 + v11;
            qe += v00*v00 + v10*v10;  qo += v01*v01 + v11*v11;
        }
        #pragma unroll
        for (int o = 4; o <= 16; o <<= 1) {
            se += __shfl_xor_sync(0xffffffff, se, o);
            so += __shfl_xor_sync(0xffffffff, so, o);
            qe += __shfl_xor_sync(0xffffffff, qe, o);
            qo += __shfl_xor_sync(0xffffffff, qo, o);
        }
        if (lane < 4) s_red[warp*32 + nt*4 + lane] = make_float4(se, so, qe, qo);
    }
    __syncthreads();
    if (t < NT) {
        int nt = t >> 3, cp = (t & 7) >> 1, odd = t & 1;
        double ds = 0.0, dq = 0.0;
        #pragma unroll
        for (int w8 = 0; w8 < 8; w8++) {
            float4 f = s_red[w8*32 + nt*4 + cp];
            ds += (double)(odd ? f.y : f.x);
            dq += (double)(odd ? f.w : f.z);
        }
        double* st = g_stats + (long)stage*CLIPS*256 + clip*256;
        atomicAdd(&st[co0 + t], ds);
        atomicAdd(&st[128 + co0 + t], dq);
    }
}

// ---------------- pack kernels ----------------
__global__ void pack_x_k(const float* __restrict__ x, int base, int count)
{
    int idx = blockIdx.x*blockDim.x + threadIdx.x;
    if (idx >= count) return;
    idx += base;
    int w = idx % 96; int t2 = idx / 96;
    int h = t2 % 96; t2 /= 96;
    int d = t2 % 16; t2 /= 16;
    int ci = t2 % 3; t2 /= 3;
    int nb = t2 % 4; int clip = t2 / 4;
    float v = x[(((long)(nb*3+ci)*64 + clip*8 + d)*96 + h)*96 + w];
    g_xpk[((((long)(clip*4+nb)*3 + ci)*18 + d+1)*98 + h+1)*98 + w+1] = packbf(v);
}

__global__ void pack_w_all_k(const float* __restrict__ w1, const float* __restrict__ w2,
                             const float* __restrict__ w3)
{
    int idx = blockIdx.x*blockDim.x + threadIdx.x;
    const float* w; u32 *dh, *dl; int kreal, kp2, rel;
    if (idx < 1536)        { w = w1; dh = g_w1hi; dl = g_w1lo; kreal = 81;   kp2 = 48;  rel = idx; }
    else if (idx < 29184)  { w = w2; dh = g_w2hi; dl = g_w2lo; kreal = 864;  kp2 = 432; rel = idx - 1536; }
    else if (idx < 139776) { w = w3; dh = g_w3hi; dl = g_w3lo; kreal = 1728; kp2 = 864; rel = idx - 29184; }
    else return;
    int co = rel / kp2, kp = rel - co*kp2;
    int k0 = 2*kp;
    float v0 = (k0   < kreal) ? w[(long)co*kreal + k0]   : 0.f;
    float v1 = (k0+1 < kreal) ? w[(long)co*kreal + k0+1] : 0.f;
    u32 p0 = packbf(v0), p1 = packbf(v1);
    dh[rel] = ((p1 >> 16) << 16) | (p0 >> 16);
    dl[rel] = ((p1 & 0xffffu) << 16) | (p0 & 0xffffu);
}

// ---------------- finalize stats (re-zeros accumulators) ----------------
__global__ void finalize_stats_k(const float* __restrict__ gma, const float* __restrict__ bet,
                                 int stage, int C, double cnt)
{
    int clip = blockIdx.x, c = threadIdx.x;
    if (c < C) {
        double* st = g_stats + (long)stage*CLIPS*256 + clip*256;
        double m = st[c] / cnt;
        double v = st[128 + c] / cnt - m*m;
        st[c] = 0.0; st[128 + c] = 0.0;
        double sc = (double)gma[c] / sqrt(v + 1e-5);
        g_scale[clip*128 + c] = (float)sc;
        g_shift[clip*128 + c] = (float)((double)bet[c] - m*sc);
    }
}

// ---------------- BN + ReLU + maxpool(1,2,2) -> packed padded out (templated) ----------------
template<int C, int H, int W>
__global__ void bn_maxpool_pk_k(const float* __restrict__ y, u32* __restrict__ out)
{
    constexpr int HO = H/2, WO = W/2;
    constexpr int POH = HO+2, POW = WO+2;
    int o = blockIdx.x*256 + threadIdx.x;
    int wo = o % WO; int t = o / WO;
    int ho = t % HO; t /= HO;
    int d  = t % CF; t /= CF;
    int c  = t % C;  t /= C;
    int clip = t >> 2;
    float sc = g_scale[clip*128 + c], sh = g_shift[clip*128 + c];
    const float* p = y + (((long)(t*C + c)*CF + d)*H + 2*ho)*W + 2*wo;
    float2 r0 = *(const float2*)p;
    float2 r1 = *(const float2*)(p + W);
    float a0 = fmaxf(fmaf(sc, r0.x, sh), 0.f);
    float a1 = fmaxf(fmaf(sc, r0.y, sh), 0.f);
    float a2 = fmaxf(fmaf(sc, r1.x, sh), 0.f);
    float a3 = fmaxf(fmaf(sc, r1.y, sh), 0.f);
    float v = fmaxf(fmaxf(a0,a1), fmaxf(a2,a3));
    out[(((long)(t*C + c)*18 + d+1)*POH + ho+1)*POW + wo+1] = packbf(v);
}

// ---------------- BN + ReLU + avgpool 6x6 -> flattened h ----------------
__global__ void bn_avgpool_k(const float* __restrict__ y)
{
    int idx = blockIdx.x*blockDim.x + threadIdx.x;
    if (idx >= CLIPS*BB*128*16*16) return;
    int wo = idx & 3;
    int ho = (idx >> 2) & 3;
    int d  = (idx >> 4) & 15;
    int c  = (idx >> 8) & 127;
    int n  = (idx >> 15) & 3;
    int clip = idx >> 17;
    float sc = g_scale[clip*128 + c], sh = g_shift[clip*128 + c];
    const float* p = y + ((((long)(clip*BB+n)*128 + c)*CF + d)*24 + 6*ho)*24 + 6*wo;
    float s = 0.f;
    #pragma unroll
    for (int i=0;i<6;i++)
        #pragma unroll
        for (int j=0;j<6;j++)
            s += fmaxf(fmaf(sc, p[i*24+j], sh), 0.f);
    g_h[(long)(clip*BB+n)*32768 + c*256 + d*16 + ho*4 + wo] = s * (1.f/36.f);
}

// ---------------- batched projection ----------------
__global__ void proj_k(const float* __restrict__ pw, const float* __restrict__ pb)
{
    int co = blockIdx.x;
    int t = threadIdx.x;
    float part[28];
    #pragma unroll
    for (int r=0;r<28;r++) part[r] = 0.f;
    const float* wrow = pw + (long)co*32768;
    for (int j = t; j < 32768; j += 256) {
        float wv = wrow[j];
        #pragma unroll
        for (int r=0;r<28;r++)
            part[r] = fmaf(wv, g_h[(long)r*32768 + j], part[r]);
    }
    #pragma unroll
    for (int r=0;r<28;r++)
        #pragma unroll
        for (int o=16;o>0;o>>=1)
            part[r] += __shfl_xor_sync(0xffffffff, part[r], o);
    __shared__ float sred[28][8];
    int wa = t >> 5, l = t & 31;
    if (l == 0) {
        #pragma unroll
        for (int r=0;r<28;r++) sred[r][wa] = part[r];
    }
    __syncthreads();
    if (t < 28) {
        float a = 0.f;
        #pragma unroll
        for (int k=0;k<8;k++) a += sred[t][k];
        int clip = t >> 2, b_ = t & 3;
        g_feat[(b_*CLIPS + clip)*DC + co] = a + pb[co];
    }
}

// ---------------- VQ argmin ----------------
__global__ void quant_score_k(const float* __restrict__ cb)
{
    int row = blockIdx.x;
    int k = blockIdx.y*256 + threadIdx.x;
    __shared__ float sf[DC];
    sf[threadIdx.x] = g_feat[row*DC + threadIdx.x];
    __syncthreads();
    const float4* c4 = (const float4*)(cb + (long)k*DC);
    const float4* f4 = (const float4*)sf;
    float dot = 0.f, cn = 0.f;
    #pragma unroll 8
    for (int j=0; j<64; j++) {
        float4 c = c4[j]; float4 f = f4[j];
        dot = fmaf(c.x,f.x,dot); dot = fmaf(c.y,f.y,dot);
        dot = fmaf(c.z,f.z,dot); dot = fmaf(c.w,f.w,dot);
        cn  = fmaf(c.x,c.x,cn);  cn  = fmaf(c.y,c.y,cn);
        cn  = fmaf(c.z,c.z,cn);  cn  = fmaf(c.w,c.w,cn);
    }
    float score = cn - 2.f*dot;
    __shared__ float ss[256];
    __shared__ int   si[256];
    ss[threadIdx.x] = score; si[threadIdx.x] = k;
    __syncthreads();
    for (int o=128; o>0; o>>=1) {
        if (threadIdx.x < o) {
            float s2 = ss[threadIdx.x+o]; int i2 = si[threadIdx.x+o];
            if (s2 < ss[threadIdx.x] || (s2 == ss[threadIdx.x] && i2 < si[threadIdx.x])) {
                ss[threadIdx.x] = s2; si[threadIdx.x] = i2;
            }
        }
        __syncthreads();
    }
    if (threadIdx.x == 0) { g_part_s[row*32+blockIdx.y] = ss[0]; g_part_i[row*32+blockIdx.y] = si[0]; }
}

__global__ void quant_reduce_k(const float* __restrict__ cb)
{
    int row = blockIdx.x;
    __shared__ int bi;
    if (threadIdx.x == 0) {
        float s = g_part_s[row*32]; int i = g_part_i[row*32];
        for (int j=1; j<32; j++) {
            float s2 = g_part_s[row*32+j]; int i2 = g_part_i[row*32+j];
            if (s2 < s || (s2 == s && i2 < i)) { s = s2; i = i2; }
        }
        g_tok[row] = i; bi = i;
    }
    __syncthreads();
    const float* crow = cb + (long)bi*DC;
    for (int j = threadIdx.x; j < DC; j += blockDim.x)
        g_quant[row*DC+j] = crow[j];
}

// ---------------- GRU input gates ----------------
__global__ void gru_gx_k(const float* __restrict__ wih, const float* __restrict__ bih)
{
    int bt = blockIdx.x;
    int g = blockIdx.y*128 + threadIdx.x;
    int b_ = bt/6, t = bt%6;
    __shared__ float sq[DC];
    sq[threadIdx.x]     = g_quant[(b_*CLIPS+t)*DC + threadIdx.x];
    sq[threadIdx.x+128] = g_quant[(b_*CLIPS+t)*DC + 128 + threadIdx.x];
    __syncthreads();
    const float4* w4 = (const float4*)(wih + (long)g*DC);
    const float4* q4 = (const float4*)sq;
    float a = bih[g];
    #pragma unroll 8
    for (int j=0;j<64;j++) {
        float4 w = w4[j], q = q4[j];
        a = fmaf(w.x,q.x,a); a = fmaf(w.y,q.y,a); a = fmaf(w.z,q.z,a); a = fmaf(w.w,q.w,a);
    }
    g_gx[bt*768 + g] = a;
}

// ---------------- fused GRU recurrence ----------------
__global__ void gru_fused_k(const float* __restrict__ whh, const float* __restrict__ bhh)
{
    int b_ = blockIdx.x, d = threadIdx.x;
    __shared__ float s_h[DC];
    s_h[d] = 0.f;
    __syncthreads();
    const float4* wr4 = (const float4*)(whh + (long)d*DC);
    const float4* wz4 = (const float4*)(whh + (long)(256+d)*DC);
    const float4* wn4 = (const float4*)(whh + (long)(512+d)*DC);
    float br = bhh[d], bz = bhh[256+d], bn_ = bhh[512+d];
    for (int t=0; t<6; t++) {
        float hr = br, hz = bz, hn = bn_;
        const float4* h4 = (const float4*)s_h;
        #pragma unroll 8
        for (int j=0; j<64; j++) {
            float4 h = h4[j];
            float4 a = wr4[j], bzv = wz4[j], c = wn4[j];
            hr = fmaf(a.x,h.x,hr); hr = fmaf(a.y,h.y,hr); hr = fmaf(a.z,h.z,hr); hr = fmaf(a.w,h.w,hr);
            hz = fmaf(bzv.x,h.x,hz); hz = fmaf(bzv.y,h.y,hz); hz = fmaf(bzv.z,h.z,hz); hz = fmaf(bzv.w,h.w,hz);
            hn = fmaf(c.x,h.x,hn); hn = fmaf(c.y,h.y,hn); hn = fmaf(c.z,h.z,hn); hn = fmaf(c.w,h.w,hn);
        }
        int bt = b_*6 + t;
        float xr = g_gx[bt*768 + d];
        float xz = g_gx[bt*768 + 256 + d];
        float xn = g_gx[bt*768 + 512 + d];
        float r = 1.f/(1.f + expf(-(xr+hr)));
        float z = 1.f/(1.f + expf(-(xz+hz)));
        float nn = tanhf(xn + r*hn);
        float h2 = (1.f - z)*nn + z*s_h[d];
        __syncthreads();
        s_h[d] = h2;
        g_ctx[bt*DC + d] = h2;
        __syncthreads();
    }
}

// ---------------- fused losses + output assembly ----------------
__global__ void loss_final_k(float* __restrict__ out)
{
    int t = threadIdx.x;
    float s0 = 0.f, s1 = 0.f;
    for (int i = t; i < BB*CLIPS*DC; i += 256) {
        float dd = g_feat[i] - g_quant[i];
        s0 = fmaf(dd, dd, s0);
    }
    for (int i = t; i < BB*6*DC; i += 256) {
        int d = i % DC; int tt = (i/DC) % 6; int b_ = i/(6*DC);
        float diff = g_ctx[i] - g_feat[(b_*CLIPS + tt + 1)*DC + d];
        s1 = fmaf(diff, diff, s1);
    }
    __shared__ float sh0[256], sh1[256];
    sh0[t] = s0; sh1[t] = s1; __syncthreads();
    for (int o=128; o>0; o>>=1) {
        if (t < o) { sh0[t] += sh0[t+o]; sh1[t] += sh1[t+o]; }
        __syncthreads();
    }
    for (int i = t; i < BB*CLIPS; i += 256) out[i] = (float)g_tok[i];
    for (int i = t; i < BB*CLIPS*DC; i += 256) out[28 + i] = g_quant[i];
    if (t == 0) {
        float c = sh0[0] / (float)(BB*CLIPS*DC);
        float x = sh1[0] / (float)(BB*6*DC);
        out[28 + 7168 + 0] = c;
        out[28 + 7168 + 1] = c;
        out[28 + 7168 + 2] = x;
        out[28 + 7168 + 3] = c + 0.25f*c + 0.1f*x;
    }
}

// ---------------- host launcher ----------------
extern "C" void kernel_launch(void* const* d_in, const int* in_sizes, int n_in,
                              void* d_out, int out_size)
{
    const float* x   = (const float*)d_in[0];
    const float* c1w = (const float*)d_in[1];
    const float* c1b = (const float*)d_in[2];
    const float* g1  = (const float*)d_in[3];
    const float* b1  = (const float*)d_in[4];
    const float* c2w = (const float*)d_in[5];
    const float* c2b = (const float*)d_in[6];
    const float* g2  = (const float*)d_in[7];
    const float* b2  = (const float*)d_in[8];
    const float* c3w = (const float*)d_in[9];
    const float* c3b = (const float*)d_in[10];
    const float* g3  = (const float*)d_in[11];
    const float* b3  = (const float*)d_in[12];
    const float* pw  = (const float*)d_in[13];
    const float* pb  = (const float*)d_in[14];
    const float* cb  = (const float*)d_in[15];
    const float* wih = (const float*)d_in[16];
    const float* whh = (const float*)d_in[17];
    const float* bih = (const float*)d_in[18];
    const float* bhh = (const float*)d_in[19];
    float* out = (float*)d_out;

    float *y1, *y2, *y3;
    u32 *xpk, *p1pk, *p2pk;
    u32 *w1hi, *w1lo, *w2hi, *w2lo, *w3hi, *w3lo;
    cudaGetSymbolAddress((void**)&y1, g_y1);
    cudaGetSymbolAddress((void**)&y2, g_y2);
    cudaGetSymbolAddress((void**)&y3, g_y3);
    cudaGetSymbolAddress((void**)&xpk, g_xpk);
    cudaGetSymbolAddress((void**)&p1pk, g_p1pk);
    cudaGetSymbolAddress((void**)&p2pk, g_p2pk);
    cudaGetSymbolAddress((void**)&w1hi, g_w1hi);
    cudaGetSymbolAddress((void**)&w1lo, g_w1lo);
    cudaGetSymbolAddress((void**)&w2hi, g_w2hi);
    cudaGetSymbolAddress((void**)&w2lo, g_w2lo);
    cudaGetSymbolAddress((void**)&w3hi, g_w3hi);
    cudaGetSymbolAddress((void**)&w3lo, g_w3lo);

    const int sm1 = (TUPW + 96)   * 4;
    const int sm2 = (TUPW + 864)  * 4;
    const int sm3 = (TUPW + 1728) * 4;
    cudaFuncSetAttribute(convmma_k<3,32,96,96,81,3,3>,
                         cudaFuncAttributeMaxDynamicSharedMemorySize, sm1);
    cudaFuncSetAttribute(convmma_k<32,64,48,48,864,27,2>,
                         cudaFuncAttributeMaxDynamicSharedMemorySize, sm2);
    cudaFuncSetAttribute(convmma_k<64,64,24,24,1728,54,2>,
                         cudaFuncAttributeMaxDynamicSharedMemorySize, sm3);

    // ---- pack (conv1 stays at launch idx 3 for ncu) ----
    const int XTOT = CLIPS*BB*3*16*96*96;
    const int XHALF = XTOT/2;
    pack_x_k<<<(XHALF + 255)/256, 256>>>(x, 0, XHALF);                 // 0
    pack_x_k<<<(XTOT - XHALF + 255)/256, 256>>>(x, XHALF, XTOT-XHALF); // 1
    pack_w_all_k<<<(139776 + 255)/256, 256>>>(c1w, c2w, c3w);          // 2

    // stage 1: conv1 -> [28][32][16][96][96]                          // 3 (profiled)
    convmma_k<3,32,96,96,81,3,3><<<dim3(576,1,28), 256, sm1>>>(
        xpk, (long)3*18*98*98, w1hi, w1lo, c1b, y1, 32, 0);
    finalize_stats_k<<<CLIPS,128>>>(g1, b1, 0, 32, (double)(BB*16*96*96));
    bn_maxpool_pk_k<32,96,96><<<129024,256>>>(y1, p1pk);

    // stage 2: conv2 -> [28][64][16][48][48]
    convmma_k<32,64,48,48,864,27,2><<<dim3(144,1,28), 256, sm2>>>(
        p1pk, (long)32*18*50*50, w2hi, w2lo, c2b, y2, 64, 1);
    finalize_stats_k<<<CLIPS,128>>>(g2, b2, 1, 64, (double)(BB*16*48*48));
    bn_maxpool_pk_k<64,48,48><<<64512,256>>>(y2, p2pk);

    // stage 3: conv3 -> [28][128][16][24][24]
    convmma_k<64,64,24,24,1728,54,2><<<dim3(36,2,28), 256, sm3>>>(
        p2pk, (long)64*18*26*26, w3hi, w3lo, c3b, y3, 128, 2);
    finalize_stats_k<<<CLIPS,128>>>(g3, b3, 2, 128, (double)(BB*16*24*24));
    bn_avgpool_k<<<3584,256>>>(y3);

    // projection + VQ + GRU + losses
    proj_k<<<256,256>>>(pw, pb);
    quant_score_k<<<dim3(28,32),256>>>(cb);
    quant_reduce_k<<<28,64>>>(cb);
    gru_gx_k<<<dim3(24,6),128>>>(wih, bih);
    gru_fused_k<<<4,256>>>(whh, bhh);
    loss_final_k<<<1,256>>>(out);
}